// round 10
// baseline (speedup 1.0000x reference)
#include <cuda_runtime.h>
#include <cuda_bf16.h>
#include <cstdint>

#define B_   64
#define T_   2048
#define C_   64
#define H_   256
#define HOR_ 96

// ---------------- scratch (device globals; no runtime allocation) ----------------
__device__ float g_cur[(size_t)B_ * T_ * H_];            // 134 MB
__device__ float g_hcomb[(size_t)B_ * T_ * (C_ + H_)];   // 168 MB
__device__ float g_gx[(size_t)B_ * T_ * 3 * H_];         // 403 MB
__device__ float g_hT[B_ * H_];

// ---------------- packed f32x2 helpers ----------------
__device__ __forceinline__ unsigned long long ffma2(unsigned long long a,
                                                    unsigned long long b,
                                                    unsigned long long c) {
    unsigned long long d;
    asm("fma.rn.f32x2 %0, %1, %2, %3;" : "=l"(d) : "l"(a), "l"(b), "l"(c));
    return d;
}
__device__ __forceinline__ float f2x_sum(unsigned long long v) {
    float lo = __uint_as_float((uint32_t)v);
    float hi = __uint_as_float((uint32_t)(v >> 32));
    return lo + hi;
}

// ---------------- f32x2 GEMM: C[M,N] = A[M,K] @ Bw[N,K]^T + bias[N] ----------------
// BM=128, BN=128, BK=16, 512 threads, 4x8 f32x2-k-packed accumulators (64 acc regs).
#define GSP 18   // padded smem row stride (floats)

__global__ void __launch_bounds__(512, 1)
gemm_f32x2_kernel(const float* __restrict__ A, const float* __restrict__ Bw,
                  const float* __restrict__ bias, float* __restrict__ C,
                  int K, int N)
{
    __shared__ float As[2][128 * GSP];
    __shared__ float Bs[2][128 * GSP];

    const int tid = threadIdx.x;
    const int tx  = tid & 15;          // n lane: cols n0 + tx + 16j (j<8)
    const int ty  = tid >> 4;          // m lane: rows m0 + ty + 32i (i<4)
    const size_t m0 = (size_t)blockIdx.y * 128;
    const int    n0 = blockIdx.x * 128;

    // loader mapping: row lr (0..127), k-quad lq (0,4,8,12)
    const int lr = tid >> 2;
    const int lq = (tid & 3) * 4;
    const float* ag = A + (m0 + lr) * (size_t)K + lq;
    const float* bg = Bw + (size_t)(n0 + lr) * K + lq;
    const int sOff = lr * GSP + lq;

    unsigned long long acc[4][8];
#pragma unroll
    for (int i = 0; i < 4; i++)
#pragma unroll
        for (int j = 0; j < 8; j++) acc[i][j] = 0ull;

    const int NT = K >> 4;

    // prologue: tile 0 -> stage 0
    {
        float4 a0 = *(const float4*)(ag);
        float4 b0 = *(const float4*)(bg);
        float* da = &As[0][sOff];
        float* db = &Bs[0][sOff];
        *(float2*)(da + 0) = make_float2(a0.x, a0.y);
        *(float2*)(da + 2) = make_float2(a0.z, a0.w);
        *(float2*)(db + 0) = make_float2(b0.x, b0.y);
        *(float2*)(db + 2) = make_float2(b0.z, b0.w);
    }
    __syncthreads();

    for (int t = 0; t < NT; t++) {
        const int p = t & 1;
        const bool more = (t + 1 < NT);
        float4 na, nb;
        if (more) {
            na = *(const float4*)(ag + (t + 1) * 16);
            nb = *(const float4*)(bg + (t + 1) * 16);
        }

        const float* Ab = As[p];
        const float* Bb = Bs[p];
#pragma unroll
        for (int kp = 0; kp < 8; kp++) {
            unsigned long long af[4], bf[8];
#pragma unroll
            for (int i = 0; i < 4; i++)
                af[i] = *(const unsigned long long*)&Ab[(ty + 32 * i) * GSP + 2 * kp];
#pragma unroll
            for (int j = 0; j < 8; j++)
                bf[j] = *(const unsigned long long*)&Bb[(tx + 16 * j) * GSP + 2 * kp];
#pragma unroll
            for (int i = 0; i < 4; i++)
#pragma unroll
                for (int j = 0; j < 8; j++)
                    acc[i][j] = ffma2(af[i], bf[j], acc[i][j]);
        }

        if (more) {
            __syncthreads();
            float* da = &As[p ^ 1][sOff];
            float* db = &Bs[p ^ 1][sOff];
            *(float2*)(da + 0) = make_float2(na.x, na.y);
            *(float2*)(da + 2) = make_float2(na.z, na.w);
            *(float2*)(db + 0) = make_float2(nb.x, nb.y);
            *(float2*)(db + 2) = make_float2(nb.z, nb.w);
            __syncthreads();
        }
    }

    float bj[8];
#pragma unroll
    for (int j = 0; j < 8; j++) bj[j] = __ldg(&bias[n0 + tx + 16 * j]);
#pragma unroll
    for (int i = 0; i < 4; i++) {
        float* cr = C + (m0 + ty + 32 * i) * (size_t)N + n0 + tx;
#pragma unroll
        for (int j = 0; j < 8; j++)
            cr[16 * j] = f2x_sum(acc[i][j]) + bj[j];
    }
}

// ---------------- copy x into hcomb[:, :, 0:64] ----------------
__global__ void copyx_kernel(const float* __restrict__ x, float* __restrict__ hcomb)
{
    int i   = blockIdx.x * 256 + threadIdx.x;   // float4 index over B*T*16
    int row = i >> 4;
    int c4  = i & 15;
    ((float4*)hcomb)[(size_t)row * 80 + c4] = ((const float4*)x)[i];
}

// ---------------- LIF scan: spikes -> hcomb[:, :, 64:320] ----------------
__global__ void lif_kernel(const float* __restrict__ cur, float* __restrict__ hcomb)
{
    int b = blockIdx.x >> 1;
    int h = (blockIdx.x & 1) * 128 + threadIdx.x;
    const float* cp = cur + ((size_t)b * T_) * H_ + h;
    float* sp = hcomb + ((size_t)b * T_) * 320 + 64 + h;

    float mem = 0.f;
#pragma unroll 8
    for (int t = 0; t < T_; t++) {
        float iv = __ldg(cp); cp += H_;
        float reset = (mem > 1.0f) ? 1.0f : 0.0f;
        mem = __fsub_rn(__fadd_rn(__fmul_rn(0.9f, mem), iv), reset);
        float spk = (mem > 1.0f) ? 1.0f : 0.0f;
        *sp = spk; sp += 320;
    }
}

// ---------------- GRU scan v2: 8-CTA clusters, 4 batches per cluster ----------------
// 16 clusters x 8 CTAs = 128 CTAs. CTA rank owns j-channels [rank*32, rank*32+32),
// all 3 gates (96 complete whh rows, 98KB, in smem). No cross-CTA k-reduction;
// only h (4 batches x 256) is broadcast via DSMEM each step.
// smem floats: wt 24576 | shH 2048 (2 buf x 4 b x 256) | shRed 3072 (12 x 8ko x 32jl)
#define GRU_SMEM_FLOATS (24576 + 2048 + 3072)
#define GRU_SMEM_BYTES  (GRU_SMEM_FLOATS * 4)   // 118784

__global__ void __cluster_dims__(8, 1, 1) __launch_bounds__(256, 1)
gru_kernel(const float* __restrict__ gx, const float* __restrict__ whh,
           const float* __restrict__ bhh, float* __restrict__ hT)
{
    extern __shared__ float smf[];
    float2* wt    = (float2*)smf;            // [3][128 k2][32 jl]
    float*  shH   = smf + 24576;             // [2 buf][4 b][256]
    float*  shRed = smf + 24576 + 2048;      // [(g*4+b)][8 ko][32 jl]

    const int tid  = threadIdx.x;
    const int rank = blockIdx.x & 7;
    const int b0   = (blockIdx.x >> 3) * 4;

    // load whh slice: rows g*256 + rank*32 + jl, k-paired
    for (int idx = tid; idx < 3 * 32 * 128; idx += 256) {
        int k2 = idx & 127;
        int rr = idx >> 7;          // 0..95
        int g  = rr >> 5;
        int jl = rr & 31;
        float2 v = *(const float2*)&whh[((size_t)(g * 256 + rank * 32 + jl)) * 256 + 2 * k2];
        wt[(g * 128 + k2) * 32 + jl] = v;
    }
    for (int idx = tid; idx < 2048; idx += 256) shH[idx] = 0.f;

    const int ko = tid >> 5;        // k-octant (32 k each)
    const int jl = tid & 31;
    const bool isGate = (tid < 128);
    const int gb = (tid >> 5) & 3;  // batch for gate stage
    const int gj = jl;

    float bh0 = 0.f, bh1 = 0.f, bh2 = 0.f;
    const float* gxp = nullptr;
    if (isGate) {
        bh0 = bhh[0 * 256 + rank * 32 + gj];
        bh1 = bhh[1 * 256 + rank * 32 + gj];
        bh2 = bhh[2 * 256 + rank * 32 + gj];
        gxp = gx + ((size_t)(b0 + gb) * T_) * 768 + rank * 32 + gj;
    }

    asm volatile("barrier.cluster.arrive.aligned;" ::: "memory");
    asm volatile("barrier.cluster.wait.aligned;" ::: "memory");

    const unsigned long long* w0p =
        (const unsigned long long*)(wt + (0 * 128 + ko * 16) * 32 + jl);
    const unsigned long long* w1p =
        (const unsigned long long*)(wt + (1 * 128 + ko * 16) * 32 + jl);
    const unsigned long long* w2p =
        (const unsigned long long*)(wt + (2 * 128 + ko * 16) * 32 + jl);

    int p = 0;
    for (int t = 0; t < T_; t++) {
        float xr = 0.f, xz = 0.f, xn = 0.f;
        if (isGate) {                        // issue early; consumed after dot loop
            xr = __ldg(gxp);
            xz = __ldg(gxp + 256);
            xn = __ldg(gxp + 512);
        }

        const unsigned long long* hp0 =
            (const unsigned long long*)(shH + p * 1024 + 0 * 256) + ko * 16;
        const unsigned long long* hp1 =
            (const unsigned long long*)(shH + p * 1024 + 1 * 256) + ko * 16;
        const unsigned long long* hp2 =
            (const unsigned long long*)(shH + p * 1024 + 2 * 256) + ko * 16;
        const unsigned long long* hp3 =
            (const unsigned long long*)(shH + p * 1024 + 3 * 256) + ko * 16;

        unsigned long long a[3][4];
#pragma unroll
        for (int g = 0; g < 3; g++)
#pragma unroll
            for (int b = 0; b < 4; b++) a[g][b] = 0ull;

#pragma unroll
        for (int k2 = 0; k2 < 16; k2++) {
            unsigned long long h0 = hp0[k2];
            unsigned long long h1 = hp1[k2];
            unsigned long long h2 = hp2[k2];
            unsigned long long h3 = hp3[k2];
            unsigned long long w0 = w0p[(size_t)k2 * 32];
            unsigned long long w1 = w1p[(size_t)k2 * 32];
            unsigned long long w2 = w2p[(size_t)k2 * 32];
            a[0][0] = ffma2(w0, h0, a[0][0]); a[0][1] = ffma2(w0, h1, a[0][1]);
            a[0][2] = ffma2(w0, h2, a[0][2]); a[0][3] = ffma2(w0, h3, a[0][3]);
            a[1][0] = ffma2(w1, h0, a[1][0]); a[1][1] = ffma2(w1, h1, a[1][1]);
            a[1][2] = ffma2(w1, h2, a[1][2]); a[1][3] = ffma2(w1, h3, a[1][3]);
            a[2][0] = ffma2(w2, h0, a[2][0]); a[2][1] = ffma2(w2, h1, a[2][1]);
            a[2][2] = ffma2(w2, h2, a[2][2]); a[2][3] = ffma2(w2, h3, a[2][3]);
        }
#pragma unroll
        for (int g = 0; g < 3; g++)
#pragma unroll
            for (int b = 0; b < 4; b++)
                shRed[((g * 4 + b) * 8 + ko) * 32 + jl] = f2x_sum(a[g][b]);
        __syncthreads();

        if (isGate) {
            float hr = 0.f, hz = 0.f, hn = 0.f;
#pragma unroll
            for (int o = 0; o < 8; o++) {
                hr += shRed[((0 * 4 + gb) * 8 + o) * 32 + gj];
                hz += shRed[((1 * 4 + gb) * 8 + o) * 32 + gj];
                hn += shRed[((2 * 4 + gb) * 8 + o) * 32 + gj];
            }
            float hold = shH[p * 1024 + gb * 256 + rank * 32 + gj];

            float r = 1.f / (1.f + expf(-(xr + hr + bh0)));
            float z = 1.f / (1.f + expf(-(xz + hz + bh1)));
            float n = tanhf(xn + r * (hn + bh2));
            float hnew = (1.f - z) * n + z * hold;

            uint32_t laddr;
            {
                const float* pdst = &shH[(p ^ 1) * 1024 + gb * 256 + rank * 32 + gj];
                asm("{ .reg .u64 tt; cvta.to.shared.u64 tt, %1; cvt.u32.u64 %0, tt; }"
                    : "=r"(laddr) : "l"(pdst));
            }
#pragma unroll
            for (int rr = 0; rr < 8; rr++) {   // broadcast h_new to all cluster CTAs
                uint32_t ra;
                asm volatile("mapa.shared::cluster.u32 %0, %1, %2;"
                             : "=r"(ra) : "r"(laddr), "r"(rr));
                asm volatile("st.shared::cluster.f32 [%0], %1;" :: "r"(ra), "f"(hnew));
            }
            if (t == T_ - 1) hT[(b0 + gb) * 256 + rank * 32 + gj] = hnew;
            gxp += 768;
        }

        asm volatile("barrier.cluster.arrive.aligned;" ::: "memory");
        asm volatile("barrier.cluster.wait.aligned;" ::: "memory");
        p ^= 1;
    }
}

// ---------------- head ----------------
__global__ void head_kernel(const float* __restrict__ hT, const float* __restrict__ W,
                            const float* __restrict__ bias, float* __restrict__ out)
{
    int b = blockIdx.x;
    int o = threadIdx.x;   // 96 threads
    const float* h = hT + b * 256;
    const float* w = W + o * 256;
    float s = bias[o];
#pragma unroll 8
    for (int j = 0; j < 256; j++) s = fmaf(h[j], w[j], s);
    out[b * 96 + o] = s;
}

// ---------------- launch ----------------
extern "C" void kernel_launch(void* const* d_in, const int* in_sizes, int n_in,
                              void* d_out, int out_size)
{
    const float* x        = (const float*)d_in[0];
    const float* snn_w    = (const float*)d_in[1];
    const float* snn_b    = (const float*)d_in[2];
    const float* gru_wih  = (const float*)d_in[3];
    const float* gru_whh  = (const float*)d_in[4];
    const float* gru_bih  = (const float*)d_in[5];
    const float* gru_bhh  = (const float*)d_in[6];
    const float* head_w   = (const float*)d_in[7];
    const float* head_b   = (const float*)d_in[8];
    float* out = (float*)d_out;

    float *cur, *hcomb, *gxb, *hTb;
    cudaGetSymbolAddress((void**)&cur,   g_cur);
    cudaGetSymbolAddress((void**)&hcomb, g_hcomb);
    cudaGetSymbolAddress((void**)&gxb,   g_gx);
    cudaGetSymbolAddress((void**)&hTb,   g_hT);

    cudaFuncSetAttribute(gru_kernel, cudaFuncAttributeMaxDynamicSharedMemorySize,
                         GRU_SMEM_BYTES);

    // 1) cur = x @ snn_w^T + snn_b            [131072,64]x[256,64]^T  (f32x2)
    gemm_f32x2_kernel<<<dim3(H_ / 128, (B_ * T_) / 128), 512>>>(x, snn_w, snn_b, cur, C_, H_);
    // 2) hcomb[:, :, 0:64] = x
    copyx_kernel<<<(B_ * T_ * C_ / 4) / 256, 256>>>(x, hcomb);
    // 3) LIF scan -> hcomb[:, :, 64:320]
    lif_kernel<<<128, 128>>>(cur, hcomb);
    // 4) gx = hcomb @ gru_wih^T + gru_bih     [131072,320]x[768,320]^T  (f32x2)
    gemm_f32x2_kernel<<<dim3(768 / 128, (B_ * T_) / 128), 512>>>(hcomb, gru_wih, gru_bih, gxb,
                                                                 C_ + H_, 3 * H_);
    // 5) GRU scan (cluster-of-8 persistent, G=4 batches, f32x2 dots)
    gru_kernel<<<128, 256, GRU_SMEM_BYTES>>>(gxb, gru_whh, gru_bhh, hTb);
    // 6) head
    head_kernel<<<B_, HOR_>>>(hTb, head_w, head_b, out);
}

// round 11
// speedup vs baseline: 1.7090x; 1.7090x over previous
#include <cuda_runtime.h>
#include <cuda_bf16.h>
#include <cstdint>

#define B_   64
#define T_   2048
#define C_   64
#define H_   256
#define HOR_ 96
#define KP   704   // expanded K: 3*64 (x split) + 2*256 (spikes x w split)

// ---------------- scratch (device globals; no runtime allocation) ----------------
__device__ float g_cur[(size_t)B_ * T_ * H_];                       // 134 MB
__device__ __align__(16) __nv_bfloat16 g_Ae[(size_t)B_ * T_ * KP];  // 185 MB
__device__ __align__(16) __nv_bfloat16 g_Be[(size_t)3 * H_ * KP];   // 1.1 MB
__device__ float g_gx[(size_t)B_ * T_ * 3 * H_];                    // 403 MB
__device__ float g_hT[B_ * H_];

// ---------------- packed f32x2 helpers ----------------
__device__ __forceinline__ unsigned long long ffma2(unsigned long long a,
                                                    unsigned long long b,
                                                    unsigned long long c) {
    unsigned long long d;
    asm("fma.rn.f32x2 %0, %1, %2, %3;" : "=l"(d) : "l"(a), "l"(b), "l"(c));
    return d;
}
__device__ __forceinline__ float f2x_sum(unsigned long long v) {
    float lo = __uint_as_float((uint32_t)v);
    float hi = __uint_as_float((uint32_t)(v >> 32));
    return lo + hi;
}
__device__ __forceinline__ uint32_t smem_u32(const void* p) {
    uint32_t a;
    asm("{ .reg .u64 tt; cvta.to.shared.u64 tt, %1; cvt.u32.u64 %0, tt; }" : "=r"(a) : "l"(p));
    return a;
}

// ---------------- f32x2 GEMM (for cur = x @ snn_w^T; threshold-sensitive, stays fp32) ----------------
#define GSP 18

__global__ void __launch_bounds__(512, 1)
gemm_f32x2_kernel(const float* __restrict__ A, const float* __restrict__ Bw,
                  const float* __restrict__ bias, float* __restrict__ C,
                  int K, int N)
{
    __shared__ float As[2][128 * GSP];
    __shared__ float Bs[2][128 * GSP];

    const int tid = threadIdx.x;
    const int tx  = tid & 15;
    const int ty  = tid >> 4;
    const size_t m0 = (size_t)blockIdx.y * 128;
    const int    n0 = blockIdx.x * 128;

    const int lr = tid >> 2;
    const int lq = (tid & 3) * 4;
    const float* ag = A + (m0 + lr) * (size_t)K + lq;
    const float* bg = Bw + (size_t)(n0 + lr) * K + lq;
    const int sOff = lr * GSP + lq;

    unsigned long long acc[4][8];
#pragma unroll
    for (int i = 0; i < 4; i++)
#pragma unroll
        for (int j = 0; j < 8; j++) acc[i][j] = 0ull;

    const int NT = K >> 4;
    {
        float4 a0 = *(const float4*)(ag);
        float4 b0 = *(const float4*)(bg);
        float* da = &As[0][sOff];
        float* db = &Bs[0][sOff];
        *(float2*)(da + 0) = make_float2(a0.x, a0.y);
        *(float2*)(da + 2) = make_float2(a0.z, a0.w);
        *(float2*)(db + 0) = make_float2(b0.x, b0.y);
        *(float2*)(db + 2) = make_float2(b0.z, b0.w);
    }
    __syncthreads();

    for (int t = 0; t < NT; t++) {
        const int p = t & 1;
        const bool more = (t + 1 < NT);
        float4 na, nb;
        if (more) {
            na = *(const float4*)(ag + (t + 1) * 16);
            nb = *(const float4*)(bg + (t + 1) * 16);
        }
        const float* Ab = As[p];
        const float* Bb = Bs[p];
#pragma unroll
        for (int kp = 0; kp < 8; kp++) {
            unsigned long long af[4], bf[8];
#pragma unroll
            for (int i = 0; i < 4; i++)
                af[i] = *(const unsigned long long*)&Ab[(ty + 32 * i) * GSP + 2 * kp];
#pragma unroll
            for (int j = 0; j < 8; j++)
                bf[j] = *(const unsigned long long*)&Bb[(tx + 16 * j) * GSP + 2 * kp];
#pragma unroll
            for (int i = 0; i < 4; i++)
#pragma unroll
                for (int j = 0; j < 8; j++)
                    acc[i][j] = ffma2(af[i], bf[j], acc[i][j]);
        }
        if (more) {
            __syncthreads();
            float* da = &As[p ^ 1][sOff];
            float* db = &Bs[p ^ 1][sOff];
            *(float2*)(da + 0) = make_float2(na.x, na.y);
            *(float2*)(da + 2) = make_float2(na.z, na.w);
            *(float2*)(db + 0) = make_float2(nb.x, nb.y);
            *(float2*)(db + 2) = make_float2(nb.z, nb.w);
            __syncthreads();
        }
    }

    float bj[8];
#pragma unroll
    for (int j = 0; j < 8; j++) bj[j] = __ldg(&bias[n0 + tx + 16 * j]);
#pragma unroll
    for (int i = 0; i < 4; i++) {
        float* cr = C + (m0 + ty + 32 * i) * (size_t)N + n0 + tx;
#pragma unroll
        for (int j = 0; j < 8; j++)
            cr[16 * j] = f2x_sum(acc[i][j]) + bj[j];
    }
}

// ---------------- split-fp32 helpers ----------------
__device__ __forceinline__ void split_bf16(float x, __nv_bfloat16& hi, __nv_bfloat16& lo) {
    hi = __float2bfloat16(x);
    lo = __float2bfloat16(x - __bfloat162float(hi));
}
__device__ __forceinline__ uint32_t pack2(__nv_bfloat16 a, __nv_bfloat16 b) {
    return (uint32_t)__bfloat16_as_ushort(a) | ((uint32_t)__bfloat16_as_ushort(b) << 16);
}

// ---------------- x -> A' cols [0:192): [xhi | xlo | xhi] ----------------
__global__ void copyx_split_kernel(const float* __restrict__ x, __nv_bfloat16* __restrict__ Ae)
{
    int i   = blockIdx.x * 256 + threadIdx.x;   // float4 index over B*T*16
    int row = i >> 4;
    int c4  = (i & 15) * 4;
    float4 v = ((const float4*)x)[i];
    __nv_bfloat16 h0, l0, h1, l1, h2, l2, h3, l3;
    split_bf16(v.x, h0, l0); split_bf16(v.y, h1, l1);
    split_bf16(v.z, h2, l2); split_bf16(v.w, h3, l3);
    uint2 hiP = make_uint2(pack2(h0, h1), pack2(h2, h3));
    uint2 loP = make_uint2(pack2(l0, l1), pack2(l2, l3));
    __nv_bfloat16* dst = Ae + (size_t)row * KP;
    *(uint2*)(dst + c4)       = hiP;
    *(uint2*)(dst + 64 + c4)  = loP;
    *(uint2*)(dst + 128 + c4) = hiP;
}

// ---------------- LIF scan: spikes (exact in bf16) -> A' cols [192:448) and [448:704) ----------------
__global__ void lif_kernel(const float* __restrict__ cur, __nv_bfloat16* __restrict__ Ae)
{
    int b = blockIdx.x >> 1;
    int h = (blockIdx.x & 1) * 128 + threadIdx.x;
    const float* cp = cur + ((size_t)b * T_) * H_ + h;
    __nv_bfloat16* sp = Ae + ((size_t)b * T_) * KP + 192 + h;

    const __nv_bfloat16 one  = __float2bfloat16(1.0f);
    const __nv_bfloat16 zero = __float2bfloat16(0.0f);
    float mem = 0.f;
#pragma unroll 8
    for (int t = 0; t < T_; t++) {
        float iv = __ldg(cp); cp += H_;
        float reset = (mem > 1.0f) ? 1.0f : 0.0f;
        mem = __fsub_rn(__fadd_rn(__fmul_rn(0.9f, mem), iv), reset);
        __nv_bfloat16 spk = (mem > 1.0f) ? one : zero;
        sp[0]   = spk;
        sp[256] = spk;
        sp += KP;
    }
}

// ---------------- gru_wih -> B' [wxhi | wxhi | wxlo | wshi | wslo] ----------------
__global__ void wih_split_kernel(const float* __restrict__ wih, __nv_bfloat16* __restrict__ Be)
{
    int idx = blockIdx.x * 256 + threadIdx.x;   // over 768*320
    int n = idx / 320;
    int c = idx - n * 320;
    __nv_bfloat16 hi, lo;
    split_bf16(wih[idx], hi, lo);
    __nv_bfloat16* dst = Be + (size_t)n * KP;
    if (c < 64) { dst[c] = hi; dst[64 + c] = hi; dst[128 + c] = lo; }
    else        { int hh = c - 64; dst[192 + hh] = hi; dst[448 + hh] = lo; }
}

// ---------------- mma.sync bf16 GEMM: gx[M,768] = A'[M,704] @ B'[768,704]^T + bih ----------------
// 128x128x32 tiles, 8 warps (2x4), warp tile 64x32, m16n8k16 HMMA, stride-40 padded smem.
#define MMS 40   // smem row stride in halves (32 + 8 pad)

__device__ __forceinline__ void ldsm_x4(uint32_t* r, uint32_t addr) {
    asm volatile("ldmatrix.sync.aligned.m8n8.x4.shared.b16 {%0,%1,%2,%3}, [%4];"
                 : "=r"(r[0]), "=r"(r[1]), "=r"(r[2]), "=r"(r[3]) : "r"(addr));
}
__device__ __forceinline__ void mma16816(float* c, const uint32_t* a, const uint32_t* b) {
    asm volatile("mma.sync.aligned.m16n8k16.row.col.f32.bf16.bf16.f32 "
                 "{%0,%1,%2,%3}, {%4,%5,%6,%7}, {%8,%9}, {%0,%1,%2,%3};"
                 : "+f"(c[0]), "+f"(c[1]), "+f"(c[2]), "+f"(c[3])
                 : "r"(a[0]), "r"(a[1]), "r"(a[2]), "r"(a[3]), "r"(b[0]), "r"(b[1]));
}

__global__ void __launch_bounds__(256, 2)
gemm_mma_kernel(const __nv_bfloat16* __restrict__ Ae, const __nv_bfloat16* __restrict__ Be,
                const float* __restrict__ bias, float* __restrict__ Cout)
{
    __shared__ __nv_bfloat16 As[2][128 * MMS];
    __shared__ __nv_bfloat16 Bs[2][128 * MMS];

    const int tid  = threadIdx.x;
    const int lane = tid & 31;
    const int warp = tid >> 5;
    const int wm   = warp >> 2;     // 0..1  (64 m-rows each)
    const int wn   = warp & 3;      // 0..3  (32 n-cols each)
    const size_t m0 = (size_t)blockIdx.y * 128;
    const int    n0 = blockIdx.x * 128;

    // loader: row = tid>>1 (0..127), 32B half = tid&1; 2 uint4 per thread per chunk
    const int lrow  = tid >> 1;
    const int lhalf = tid & 1;
    const uint4* agp = (const uint4*)(Ae + (m0 + lrow) * (size_t)KP) + lhalf * 2;
    const uint4* bgp = (const uint4*)(Be + (size_t)(n0 + lrow) * KP) + lhalf * 2;
    const int sIdx = lrow * 5 + lhalf * 2;   // uint4 index into stage (MMS=40 halves = 5 uint4)

    // fragment smem offsets (halves)
    const int arow_off = (wm * 64 + (lane & 15)) * MMS + (lane >> 4) * 8;
    const int brow_off = (wn * 32 + ((lane >> 4) & 1) * 8 + (lane & 7)) * MMS + ((lane >> 3) & 1) * 8;

    const uint32_t aB[2] = { smem_u32(As[0]), smem_u32(As[1]) };
    const uint32_t bB[2] = { smem_u32(Bs[0]), smem_u32(Bs[1]) };

    float acc[4][4][4];
#pragma unroll
    for (int mi = 0; mi < 4; mi++)
#pragma unroll
        for (int ni = 0; ni < 4; ni++)
#pragma unroll
            for (int f = 0; f < 4; f++) acc[mi][ni][f] = 0.f;

    const int NT = KP / 32;   // 22

    // prologue: chunk 0 -> stage 0
    {
        uint4 a0 = agp[0], a1 = agp[1], b0 = bgp[0], b1 = bgp[1];
        ((uint4*)As[0])[sIdx] = a0; ((uint4*)As[0])[sIdx + 1] = a1;
        ((uint4*)Bs[0])[sIdx] = b0; ((uint4*)Bs[0])[sIdx + 1] = b1;
    }
    __syncthreads();

    for (int t = 0; t < NT; t++) {
        const int p = t & 1;
        const bool more = (t + 1 < NT);
        uint4 pa0, pa1, pb0, pb1;
        if (more) {
            pa0 = agp[(t + 1) * 4]; pa1 = agp[(t + 1) * 4 + 1];
            pb0 = bgp[(t + 1) * 4]; pb1 = bgp[(t + 1) * 4 + 1];
        }

#pragma unroll
        for (int ks = 0; ks < 2; ks++) {
            uint32_t af[4][4], bf[2][4];
#pragma unroll
            for (int mi = 0; mi < 4; mi++)
                ldsm_x4(af[mi], aB[p] + (uint32_t)(arow_off + mi * (16 * MMS) + ks * 16) * 2);
#pragma unroll
            for (int n2 = 0; n2 < 2; n2++)
                ldsm_x4(bf[n2], bB[p] + (uint32_t)(brow_off + n2 * (16 * MMS) + ks * 16) * 2);
#pragma unroll
            for (int mi = 0; mi < 4; mi++)
#pragma unroll
                for (int ni = 0; ni < 4; ni++)
                    mma16816(acc[mi][ni], af[mi], &bf[ni >> 1][(ni & 1) * 2]);
        }

        if (more) {
            __syncthreads();
            ((uint4*)As[p ^ 1])[sIdx] = pa0; ((uint4*)As[p ^ 1])[sIdx + 1] = pa1;
            ((uint4*)Bs[p ^ 1])[sIdx] = pb0; ((uint4*)Bs[p ^ 1])[sIdx + 1] = pb1;
            __syncthreads();
        }
    }

    // epilogue: C frag -> gx, bias fused
#pragma unroll
    for (int ni = 0; ni < 4; ni++) {
        const int col = n0 + wn * 32 + ni * 8 + (lane & 3) * 2;
        float2 bv = *(const float2*)&bias[col];
#pragma unroll
        for (int mi = 0; mi < 4; mi++) {
            const size_t rlo = m0 + wm * 64 + mi * 16 + (lane >> 2);
            float2 o0, o1;
            o0.x = acc[mi][ni][0] + bv.x; o0.y = acc[mi][ni][1] + bv.y;
            o1.x = acc[mi][ni][2] + bv.x; o1.y = acc[mi][ni][3] + bv.y;
            *(float2*)&Cout[rlo * 768 + col]       = o0;
            *(float2*)&Cout[(rlo + 8) * 768 + col] = o1;
        }
    }
}

// ---------------- GRU scan: cluster-of-4 persistent, 2 batches per cluster (R9 version) ----------------
#define GRU_SMEM_FLOATS (3 * 128 * 64 * 2 + 1024 + 1536)
#define GRU_SMEM_BYTES  (GRU_SMEM_FLOATS * 4)             // 206848

__global__ void __cluster_dims__(4, 1, 1) __launch_bounds__(256, 1)
gru_kernel(const float* __restrict__ gx, const float* __restrict__ whh,
           const float* __restrict__ bhh, float* __restrict__ hT)
{
    extern __shared__ float smf[];
    float2* wt    = (float2*)smf;           // [3][128 k-pairs][64 jl]
    float*  shH   = smf + 49152;            // [2 buf][2 batch][256]
    float*  shRed = smf + 49152 + 1024;     // [3 gate * 2 batch][4 q][64 jl]

    const int tid  = threadIdx.x;
    const int rank = blockIdx.x & 3;
    const int b0   = (blockIdx.x >> 2) * 2;

    for (int idx = tid; idx < 3 * 64 * 128; idx += 256) {
        int rr = idx >> 7;
        int k2 = idx & 127;
        int g  = rr >> 6;
        int jl = rr & 63;
        float2 v = *(const float2*)&whh[((size_t)(g * 256 + rank * 64 + jl)) * 256 + 2 * k2];
        wt[(g * 128 + k2) * 64 + jl] = v;
    }
    for (int idx = tid; idx < 1024; idx += 256) shH[idx] = 0.f;

    const int q  = tid >> 6;
    const int jl = tid & 63;
    const bool isGate = (tid < 128);
    const int gb = (tid >> 6) & 1;
    const int gj = jl;

    float bh0 = 0.f, bh1 = 0.f, bh2 = 0.f;
    const float* gxp = nullptr;
    if (isGate) {
        bh0 = bhh[0 * 256 + rank * 64 + gj];
        bh1 = bhh[1 * 256 + rank * 64 + gj];
        bh2 = bhh[2 * 256 + rank * 64 + gj];
        gxp = gx + ((size_t)(b0 + gb) * T_) * 768 + rank * 64 + gj;
    }

    asm volatile("barrier.cluster.arrive.aligned;" ::: "memory");
    asm volatile("barrier.cluster.wait.aligned;" ::: "memory");

    const unsigned long long* w0p = (const unsigned long long*)(wt + (0 * 128 + q * 32) * 64 + jl);
    const unsigned long long* w1p = (const unsigned long long*)(wt + (1 * 128 + q * 32) * 64 + jl);
    const unsigned long long* w2p = (const unsigned long long*)(wt + (2 * 128 + q * 32) * 64 + jl);

    int p = 0;
    for (int t = 0; t < T_; t++) {
        float xr = 0.f, xz = 0.f, xn = 0.f;
        if (isGate) {
            xr = __ldg(gxp);
            xz = __ldg(gxp + 256);
            xn = __ldg(gxp + 512);
        }

        const unsigned long long* h0p = (const unsigned long long*)(shH + p * 512) + q * 32;
        const unsigned long long* h1p = (const unsigned long long*)(shH + p * 512 + 256) + q * 32;
        unsigned long long a00 = 0ull, a01 = 0ull, a10 = 0ull, a11 = 0ull, a20 = 0ull, a21 = 0ull;
#pragma unroll
        for (int k2 = 0; k2 < 32; k2++) {
            unsigned long long h0 = h0p[k2];
            unsigned long long h1 = h1p[k2];
            unsigned long long w0 = w0p[(size_t)k2 * 64];
            unsigned long long w1 = w1p[(size_t)k2 * 64];
            unsigned long long w2 = w2p[(size_t)k2 * 64];
            a00 = ffma2(w0, h0, a00);
            a01 = ffma2(w0, h1, a01);
            a10 = ffma2(w1, h0, a10);
            a11 = ffma2(w1, h1, a11);
            a20 = ffma2(w2, h0, a20);
            a21 = ffma2(w2, h1, a21);
        }
        shRed[((0 * 2 + 0) * 4 + q) * 64 + jl] = f2x_sum(a00);
        shRed[((0 * 2 + 1) * 4 + q) * 64 + jl] = f2x_sum(a01);
        shRed[((1 * 2 + 0) * 4 + q) * 64 + jl] = f2x_sum(a10);
        shRed[((1 * 2 + 1) * 4 + q) * 64 + jl] = f2x_sum(a11);
        shRed[((2 * 2 + 0) * 4 + q) * 64 + jl] = f2x_sum(a20);
        shRed[((2 * 2 + 1) * 4 + q) * 64 + jl] = f2x_sum(a21);
        __syncthreads();

        if (isGate) {
            int base0 = ((0 * 2 + gb) * 4) * 64 + gj;
            int base1 = ((1 * 2 + gb) * 4) * 64 + gj;
            int base2 = ((2 * 2 + gb) * 4) * 64 + gj;
            float hr = shRed[base0] + shRed[base0 + 64] + shRed[base0 + 128] + shRed[base0 + 192];
            float hz = shRed[base1] + shRed[base1 + 64] + shRed[base1 + 128] + shRed[base1 + 192];
            float hn = shRed[base2] + shRed[base2 + 64] + shRed[base2 + 128] + shRed[base2 + 192];
            float hold = shH[p * 512 + gb * 256 + rank * 64 + gj];

            float r = 1.f / (1.f + expf(-(xr + hr + bh0)));
            float z = 1.f / (1.f + expf(-(xz + hz + bh1)));
            float n = tanhf(xn + r * (hn + bh2));
            float hnew = (1.f - z) * n + z * hold;

            uint32_t laddr;
            {
                const float* pdst = &shH[(p ^ 1) * 512 + gb * 256 + rank * 64 + gj];
                asm("{ .reg .u64 tt; cvta.to.shared.u64 tt, %1; cvt.u32.u64 %0, tt; }"
                    : "=r"(laddr) : "l"(pdst));
            }
#pragma unroll
            for (int rr = 0; rr < 4; rr++) {
                uint32_t ra;
                asm volatile("mapa.shared::cluster.u32 %0, %1, %2;"
                             : "=r"(ra) : "r"(laddr), "r"(rr));
                asm volatile("st.shared::cluster.f32 [%0], %1;" :: "r"(ra), "f"(hnew));
            }
            if (t == T_ - 1) hT[(b0 + gb) * 256 + rank * 64 + gj] = hnew;
            gxp += 768;
        }

        asm volatile("barrier.cluster.arrive.aligned;" ::: "memory");
        asm volatile("barrier.cluster.wait.aligned;" ::: "memory");
        p ^= 1;
    }
}

// ---------------- head ----------------
__global__ void head_kernel(const float* __restrict__ hT, const float* __restrict__ W,
                            const float* __restrict__ bias, float* __restrict__ out)
{
    int b = blockIdx.x;
    int o = threadIdx.x;   // 96 threads
    const float* h = hT + b * 256;
    const float* w = W + o * 256;
    float s = bias[o];
#pragma unroll 8
    for (int j = 0; j < 256; j++) s = fmaf(h[j], w[j], s);
    out[b * 96 + o] = s;
}

// ---------------- launch ----------------
extern "C" void kernel_launch(void* const* d_in, const int* in_sizes, int n_in,
                              void* d_out, int out_size)
{
    const float* x        = (const float*)d_in[0];
    const float* snn_w    = (const float*)d_in[1];
    const float* snn_b    = (const float*)d_in[2];
    const float* gru_wih  = (const float*)d_in[3];
    const float* gru_whh  = (const float*)d_in[4];
    const float* gru_bih  = (const float*)d_in[5];
    const float* gru_bhh  = (const float*)d_in[6];
    const float* head_w   = (const float*)d_in[7];
    const float* head_b   = (const float*)d_in[8];
    float* out = (float*)d_out;

    float *cur, *gxb, *hTb;
    __nv_bfloat16 *Ae, *Be;
    cudaGetSymbolAddress((void**)&cur, g_cur);
    cudaGetSymbolAddress((void**)&Ae,  g_Ae);
    cudaGetSymbolAddress((void**)&Be,  g_Be);
    cudaGetSymbolAddress((void**)&gxb, g_gx);
    cudaGetSymbolAddress((void**)&hTb, g_hT);

    cudaFuncSetAttribute(gru_kernel, cudaFuncAttributeMaxDynamicSharedMemorySize,
                         GRU_SMEM_BYTES);

    // 1) cur = x @ snn_w^T + snn_b   (fp32 f32x2 — spike thresholds are error-sensitive)
    gemm_f32x2_kernel<<<dim3(H_ / 128, (B_ * T_) / 128), 512>>>(x, snn_w, snn_b, cur, C_, H_);
    // 2) x -> A' split columns
    copyx_split_kernel<<<(B_ * T_ * 16) / 256, 256>>>(x, Ae);
    // 3) LIF scan -> A' spike columns (exact bf16)
    lif_kernel<<<128, 128>>>(cur, Ae);
    // 4) wih -> B' split columns
    wih_split_kernel<<<(768 * 320) / 256, 256>>>(gru_wih, Be);
    // 5) gx = A' @ B'^T + bih  (mma.sync bf16 HMMA, split-fp32 accuracy)
    gemm_mma_kernel<<<dim3(768 / 128, (B_ * T_) / 128), 256>>>(Ae, Be, gru_bih, gxb);
    // 6) GRU scan (cluster-of-4 persistent, f32x2 dots)
    gru_kernel<<<128, 256, GRU_SMEM_BYTES>>>(gxb, gru_whh, gru_bhh, hTb);
    // 7) head
    head_kernel<<<B_, HOR_>>>(hTb, head_w, head_b, out);
}

// round 12
// speedup vs baseline: 1.9510x; 1.1416x over previous
#include <cuda_runtime.h>
#include <cuda_bf16.h>
#include <cstdint>

#define B_   64
#define T_   2048
#define C_   64
#define H_   256
#define HOR_ 96
#define KP   704   // expanded K: 3*64 (x split) + 2*256 (spikes x w split)

// ---------------- scratch (device globals; no runtime allocation) ----------------
__device__ float g_cur[(size_t)B_ * T_ * H_];                       // 134 MB
__device__ __align__(16) __nv_bfloat16 g_Ae[(size_t)B_ * T_ * KP];  // 185 MB
__device__ __align__(16) __nv_bfloat16 g_Be[(size_t)3 * H_ * KP];   // 1.1 MB
__device__ float g_gx[(size_t)B_ * T_ * 3 * H_];                    // 403 MB
__device__ float g_hT[B_ * H_];

// ---------------- packed f32x2 helpers ----------------
__device__ __forceinline__ unsigned long long ffma2(unsigned long long a,
                                                    unsigned long long b,
                                                    unsigned long long c) {
    unsigned long long d;
    asm("fma.rn.f32x2 %0, %1, %2, %3;" : "=l"(d) : "l"(a), "l"(b), "l"(c));
    return d;
}
__device__ __forceinline__ float f2x_sum(unsigned long long v) {
    float lo = __uint_as_float((uint32_t)v);
    float hi = __uint_as_float((uint32_t)(v >> 32));
    return lo + hi;
}
__device__ __forceinline__ uint32_t smem_u32(const void* p) {
    uint32_t a;
    asm("{ .reg .u64 tt; cvta.to.shared.u64 tt, %1; cvt.u32.u64 %0, tt; }" : "=r"(a) : "l"(p));
    return a;
}

// ---------------- f32x2 GEMM (for cur = x @ snn_w^T; threshold-sensitive, stays fp32) ----------------
#define GSP 18

__global__ void __launch_bounds__(512, 1)
gemm_f32x2_kernel(const float* __restrict__ A, const float* __restrict__ Bw,
                  const float* __restrict__ bias, float* __restrict__ C,
                  int K, int N)
{
    __shared__ float As[2][128 * GSP];
    __shared__ float Bs[2][128 * GSP];

    const int tid = threadIdx.x;
    const int tx  = tid & 15;
    const int ty  = tid >> 4;
    const size_t m0 = (size_t)blockIdx.y * 128;
    const int    n0 = blockIdx.x * 128;

    const int lr = tid >> 2;
    const int lq = (tid & 3) * 4;
    const float* ag = A + (m0 + lr) * (size_t)K + lq;
    const float* bg = Bw + (size_t)(n0 + lr) * K + lq;
    const int sOff = lr * GSP + lq;

    unsigned long long acc[4][8];
#pragma unroll
    for (int i = 0; i < 4; i++)
#pragma unroll
        for (int j = 0; j < 8; j++) acc[i][j] = 0ull;

    const int NT = K >> 4;
    {
        float4 a0 = *(const float4*)(ag);
        float4 b0 = *(const float4*)(bg);
        float* da = &As[0][sOff];
        float* db = &Bs[0][sOff];
        *(float2*)(da + 0) = make_float2(a0.x, a0.y);
        *(float2*)(da + 2) = make_float2(a0.z, a0.w);
        *(float2*)(db + 0) = make_float2(b0.x, b0.y);
        *(float2*)(db + 2) = make_float2(b0.z, b0.w);
    }
    __syncthreads();

    for (int t = 0; t < NT; t++) {
        const int p = t & 1;
        const bool more = (t + 1 < NT);
        float4 na, nb;
        if (more) {
            na = *(const float4*)(ag + (t + 1) * 16);
            nb = *(const float4*)(bg + (t + 1) * 16);
        }
        const float* Ab = As[p];
        const float* Bb = Bs[p];
#pragma unroll
        for (int kp = 0; kp < 8; kp++) {
            unsigned long long af[4], bf[8];
#pragma unroll
            for (int i = 0; i < 4; i++)
                af[i] = *(const unsigned long long*)&Ab[(ty + 32 * i) * GSP + 2 * kp];
#pragma unroll
            for (int j = 0; j < 8; j++)
                bf[j] = *(const unsigned long long*)&Bb[(tx + 16 * j) * GSP + 2 * kp];
#pragma unroll
            for (int i = 0; i < 4; i++)
#pragma unroll
                for (int j = 0; j < 8; j++)
                    acc[i][j] = ffma2(af[i], bf[j], acc[i][j]);
        }
        if (more) {
            __syncthreads();
            float* da = &As[p ^ 1][sOff];
            float* db = &Bs[p ^ 1][sOff];
            *(float2*)(da + 0) = make_float2(na.x, na.y);
            *(float2*)(da + 2) = make_float2(na.z, na.w);
            *(float2*)(db + 0) = make_float2(nb.x, nb.y);
            *(float2*)(db + 2) = make_float2(nb.z, nb.w);
            __syncthreads();
        }
    }

    float bj[8];
#pragma unroll
    for (int j = 0; j < 8; j++) bj[j] = __ldg(&bias[n0 + tx + 16 * j]);
#pragma unroll
    for (int i = 0; i < 4; i++) {
        float* cr = C + (m0 + ty + 32 * i) * (size_t)N + n0 + tx;
#pragma unroll
        for (int j = 0; j < 8; j++)
            cr[16 * j] = f2x_sum(acc[i][j]) + bj[j];
    }
}

// ---------------- split-fp32 helpers ----------------
__device__ __forceinline__ void split_bf16(float x, __nv_bfloat16& hi, __nv_bfloat16& lo) {
    hi = __float2bfloat16(x);
    lo = __float2bfloat16(x - __bfloat162float(hi));
}
__device__ __forceinline__ uint32_t pack2(__nv_bfloat16 a, __nv_bfloat16 b) {
    return (uint32_t)__bfloat16_as_ushort(a) | ((uint32_t)__bfloat16_as_ushort(b) << 16);
}

// ---------------- x -> A' cols [0:192): [xhi | xlo | xhi] ----------------
__global__ void copyx_split_kernel(const float* __restrict__ x, __nv_bfloat16* __restrict__ Ae)
{
    int i   = blockIdx.x * 256 + threadIdx.x;   // float4 index over B*T*16
    int row = i >> 4;
    int c4  = (i & 15) * 4;
    float4 v = ((const float4*)x)[i];
    __nv_bfloat16 h0, l0, h1, l1, h2, l2, h3, l3;
    split_bf16(v.x, h0, l0); split_bf16(v.y, h1, l1);
    split_bf16(v.z, h2, l2); split_bf16(v.w, h3, l3);
    uint2 hiP = make_uint2(pack2(h0, h1), pack2(h2, h3));
    uint2 loP = make_uint2(pack2(l0, l1), pack2(l2, l3));
    __nv_bfloat16* dst = Ae + (size_t)row * KP;
    *(uint2*)(dst + c4)       = hiP;
    *(uint2*)(dst + 64 + c4)  = loP;
    *(uint2*)(dst + 128 + c4) = hiP;
}

// ---------------- LIF scan: spikes (exact in bf16) -> A' cols [192:448) and [448:704) ----------------
__global__ void lif_kernel(const float* __restrict__ cur, __nv_bfloat16* __restrict__ Ae)
{
    int b = blockIdx.x >> 1;
    int h = (blockIdx.x & 1) * 128 + threadIdx.x;
    const float* cp = cur + ((size_t)b * T_) * H_ + h;
    __nv_bfloat16* sp = Ae + ((size_t)b * T_) * KP + 192 + h;

    const __nv_bfloat16 one  = __float2bfloat16(1.0f);
    const __nv_bfloat16 zero = __float2bfloat16(0.0f);
    float mem = 0.f;
#pragma unroll 8
    for (int t = 0; t < T_; t++) {
        float iv = __ldg(cp); cp += H_;
        float reset = (mem > 1.0f) ? 1.0f : 0.0f;
        mem = __fsub_rn(__fadd_rn(__fmul_rn(0.9f, mem), iv), reset);
        __nv_bfloat16 spk = (mem > 1.0f) ? one : zero;
        sp[0]   = spk;
        sp[256] = spk;
        sp += KP;
    }
}

// ---------------- gru_wih -> B' [wxhi | wxhi | wxlo | wshi | wslo] ----------------
__global__ void wih_split_kernel(const float* __restrict__ wih, __nv_bfloat16* __restrict__ Be)
{
    int idx = blockIdx.x * 256 + threadIdx.x;   // over 768*320
    int n = idx / 320;
    int c = idx - n * 320;
    __nv_bfloat16 hi, lo;
    split_bf16(wih[idx], hi, lo);
    __nv_bfloat16* dst = Be + (size_t)n * KP;
    if (c < 64) { dst[c] = hi; dst[64 + c] = hi; dst[128 + c] = lo; }
    else        { int hh = c - 64; dst[192 + hh] = hi; dst[448 + hh] = lo; }
}

// ---------------- mma.sync bf16 GEMM: gx[M,768] = A'[M,704] @ B'[768,704]^T + bih ----------------
#define MMS 40   // smem row stride in halves (32 + 8 pad)

__device__ __forceinline__ void ldsm_x4(uint32_t* r, uint32_t addr) {
    asm volatile("ldmatrix.sync.aligned.m8n8.x4.shared.b16 {%0,%1,%2,%3}, [%4];"
                 : "=r"(r[0]), "=r"(r[1]), "=r"(r[2]), "=r"(r[3]) : "r"(addr));
}
__device__ __forceinline__ void mma16816(float* c, const uint32_t* a, const uint32_t* b) {
    asm volatile("mma.sync.aligned.m16n8k16.row.col.f32.bf16.bf16.f32 "
                 "{%0,%1,%2,%3}, {%4,%5,%6,%7}, {%8,%9}, {%0,%1,%2,%3};"
                 : "+f"(c[0]), "+f"(c[1]), "+f"(c[2]), "+f"(c[3])
                 : "r"(a[0]), "r"(a[1]), "r"(a[2]), "r"(a[3]), "r"(b[0]), "r"(b[1]));
}

__global__ void __launch_bounds__(256, 2)
gemm_mma_kernel(const __nv_bfloat16* __restrict__ Ae, const __nv_bfloat16* __restrict__ Be,
                const float* __restrict__ bias, float* __restrict__ Cout)
{
    __shared__ __nv_bfloat16 As[2][128 * MMS];
    __shared__ __nv_bfloat16 Bs[2][128 * MMS];

    const int tid  = threadIdx.x;
    const int lane = tid & 31;
    const int warp = tid >> 5;
    const int wm   = warp >> 2;
    const int wn   = warp & 3;
    const size_t m0 = (size_t)blockIdx.y * 128;
    const int    n0 = blockIdx.x * 128;

    const int lrow  = tid >> 1;
    const int lhalf = tid & 1;
    const uint4* agp = (const uint4*)(Ae + (m0 + lrow) * (size_t)KP) + lhalf * 2;
    const uint4* bgp = (const uint4*)(Be + (size_t)(n0 + lrow) * KP) + lhalf * 2;
    const int sIdx = lrow * 5 + lhalf * 2;

    const int arow_off = (wm * 64 + (lane & 15)) * MMS + (lane >> 4) * 8;
    const int brow_off = (wn * 32 + ((lane >> 4) & 1) * 8 + (lane & 7)) * MMS + ((lane >> 3) & 1) * 8;

    const uint32_t aB[2] = { smem_u32(As[0]), smem_u32(As[1]) };
    const uint32_t bB[2] = { smem_u32(Bs[0]), smem_u32(Bs[1]) };

    float acc[4][4][4];
#pragma unroll
    for (int mi = 0; mi < 4; mi++)
#pragma unroll
        for (int ni = 0; ni < 4; ni++)
#pragma unroll
            for (int f = 0; f < 4; f++) acc[mi][ni][f] = 0.f;

    const int NT = KP / 32;   // 22

    {
        uint4 a0 = agp[0], a1 = agp[1], b0 = bgp[0], b1 = bgp[1];
        ((uint4*)As[0])[sIdx] = a0; ((uint4*)As[0])[sIdx + 1] = a1;
        ((uint4*)Bs[0])[sIdx] = b0; ((uint4*)Bs[0])[sIdx + 1] = b1;
    }
    __syncthreads();

    for (int t = 0; t < NT; t++) {
        const int p = t & 1;
        const bool more = (t + 1 < NT);
        uint4 pa0, pa1, pb0, pb1;
        if (more) {
            pa0 = agp[(t + 1) * 4]; pa1 = agp[(t + 1) * 4 + 1];
            pb0 = bgp[(t + 1) * 4]; pb1 = bgp[(t + 1) * 4 + 1];
        }

#pragma unroll
        for (int ks = 0; ks < 2; ks++) {
            uint32_t af[4][4], bf[2][4];
#pragma unroll
            for (int mi = 0; mi < 4; mi++)
                ldsm_x4(af[mi], aB[p] + (uint32_t)(arow_off + mi * (16 * MMS) + ks * 16) * 2);
#pragma unroll
            for (int n2 = 0; n2 < 2; n2++)
                ldsm_x4(bf[n2], bB[p] + (uint32_t)(brow_off + n2 * (16 * MMS) + ks * 16) * 2);
#pragma unroll
            for (int mi = 0; mi < 4; mi++)
#pragma unroll
                for (int ni = 0; ni < 4; ni++)
                    mma16816(acc[mi][ni], af[mi], &bf[ni >> 1][(ni & 1) * 2]);
        }

        if (more) {
            __syncthreads();
            ((uint4*)As[p ^ 1])[sIdx] = pa0; ((uint4*)As[p ^ 1])[sIdx + 1] = pa1;
            ((uint4*)Bs[p ^ 1])[sIdx] = pb0; ((uint4*)Bs[p ^ 1])[sIdx + 1] = pb1;
            __syncthreads();
        }
    }

#pragma unroll
    for (int ni = 0; ni < 4; ni++) {
        const int col = n0 + wn * 32 + ni * 8 + (lane & 3) * 2;
        float2 bv = *(const float2*)&bias[col];
#pragma unroll
        for (int mi = 0; mi < 4; mi++) {
            const size_t rlo = m0 + wm * 64 + mi * 16 + (lane >> 2);
            float2 o0, o1;
            o0.x = acc[mi][ni][0] + bv.x; o0.y = acc[mi][ni][1] + bv.y;
            o1.x = acc[mi][ni][2] + bv.x; o1.y = acc[mi][ni][3] + bv.y;
            *(float2*)&Cout[rlo * 768 + col]       = o0;
            *(float2*)&Cout[(rlo + 8) * 768 + col] = o1;
        }
    }
}

// ---------------- GRU scan v3: 4-CTA clusters, 2 batches, weights in REGISTERS ----------------
// 384 threads: slot = tid>>6 in [0,6) -> (gate g = slot>>1, k-half hk = slot&1); jl = tid&63.
// Thread holds whh row (g*256 + rank*64 + jl), k-range [hk*128, hk*128+128) in 64 f32x2 regs.
// Per-step smem traffic: h broadcast reads (LDS.128, 1 phase each) + tiny shRed.
__global__ void __cluster_dims__(4, 1, 1) __launch_bounds__(384, 1)
gru_kernel(const float* __restrict__ gx, const float* __restrict__ whh,
           const float* __restrict__ bhh, float* __restrict__ hT)
{
    __shared__ float shH[1024];    // [2 buf][2 batch][256]
    __shared__ float shRed[768];   // [(g*2+hk)*2 + b][64 jl]

    const int tid  = threadIdx.x;
    const int rank = blockIdx.x & 3;
    const int b0   = (blockIdx.x >> 2) * 2;
    const int slot = tid >> 6;     // 0..5
    const int g    = slot >> 1;
    const int hk   = slot & 1;
    const int jl   = tid & 63;

    // time-invariant weights -> registers (64 f32x2 = this thread's 128-k row-half)
    unsigned long long w[64];
    {
        const ulonglong2* wp = (const ulonglong2*)(
            whh + ((size_t)(g * 256 + rank * 64 + jl)) * 256 + hk * 128);
#pragma unroll
        for (int i = 0; i < 32; i++) {
            ulonglong2 v = wp[i];
            w[2 * i]     = v.x;
            w[2 * i + 1] = v.y;
        }
    }
    for (int idx = tid; idx < 1024; idx += 384) shH[idx] = 0.f;

    const bool isGate = (tid < 128);
    const int gb = (tid >> 6) & 1;     // batch for gate stage (valid when isGate)
    const int gj = jl;

    float bh0 = 0.f, bh1 = 0.f, bh2 = 0.f;
    const float* gxp = nullptr;
    if (isGate) {
        bh0 = bhh[0 * 256 + rank * 64 + gj];
        bh1 = bhh[1 * 256 + rank * 64 + gj];
        bh2 = bhh[2 * 256 + rank * 64 + gj];
        gxp = gx + ((size_t)(b0 + gb) * T_) * 768 + rank * 64 + gj;
    }

    __syncthreads();
    asm volatile("barrier.cluster.arrive.aligned;" ::: "memory");
    asm volatile("barrier.cluster.wait.aligned;" ::: "memory");

    int p = 0;
    for (int t = 0; t < T_; t++) {
        float xr = 0.f, xz = 0.f, xn = 0.f;
        if (isGate) {                  // issue early; consumed after dot loop
            xr = __ldg(gxp);
            xz = __ldg(gxp + 256);
            xn = __ldg(gxp + 512);
        }

        // h slices for both batches: 32 x 16B broadcast loads each
        const ulonglong2* hp0 = ((const ulonglong2*)shH) + p * 128 + 0 * 64 + hk * 32;
        const ulonglong2* hp1 = ((const ulonglong2*)shH) + p * 128 + 1 * 64 + hk * 32;

        unsigned long long a0 = 0ull, a0b = 0ull, a1 = 0ull, a1b = 0ull;
#pragma unroll
        for (int i = 0; i < 32; i++) {
            ulonglong2 h0 = hp0[i];
            ulonglong2 h1 = hp1[i];
            a0  = ffma2(w[2 * i],     h0.x, a0);
            a0b = ffma2(w[2 * i + 1], h0.y, a0b);
            a1  = ffma2(w[2 * i],     h1.x, a1);
            a1b = ffma2(w[2 * i + 1], h1.y, a1b);
        }
        shRed[(slot * 2 + 0) * 64 + jl] = f2x_sum(a0) + f2x_sum(a0b);
        shRed[(slot * 2 + 1) * 64 + jl] = f2x_sum(a1) + f2x_sum(a1b);
        __syncthreads();

        if (isGate) {
            // gate g sums its two k-halves: slots g*2 and g*2+1 -> indices (g*4+gb), (g*4+2+gb)
            float hr = shRed[(0 * 4 + gb) * 64 + gj] + shRed[(0 * 4 + 2 + gb) * 64 + gj];
            float hz = shRed[(1 * 4 + gb) * 64 + gj] + shRed[(1 * 4 + 2 + gb) * 64 + gj];
            float hn = shRed[(2 * 4 + gb) * 64 + gj] + shRed[(2 * 4 + 2 + gb) * 64 + gj];
            float hold = shH[p * 512 + gb * 256 + rank * 64 + gj];

            float r = 1.f / (1.f + expf(-(xr + hr + bh0)));
            float z = 1.f / (1.f + expf(-(xz + hz + bh1)));
            float n = tanhf(xn + r * (hn + bh2));
            float hnew = (1.f - z) * n + z * hold;

            uint32_t laddr;
            {
                const float* pdst = &shH[(p ^ 1) * 512 + gb * 256 + rank * 64 + gj];
                asm("{ .reg .u64 tt; cvta.to.shared.u64 tt, %1; cvt.u32.u64 %0, tt; }"
                    : "=r"(laddr) : "l"(pdst));
            }
#pragma unroll
            for (int rr = 0; rr < 4; rr++) {   // broadcast h_new to all cluster CTAs
                uint32_t ra;
                asm volatile("mapa.shared::cluster.u32 %0, %1, %2;"
                             : "=r"(ra) : "r"(laddr), "r"(rr));
                asm volatile("st.shared::cluster.f32 [%0], %1;" :: "r"(ra), "f"(hnew));
            }
            if (t == T_ - 1) hT[(b0 + gb) * 256 + rank * 64 + gj] = hnew;
            gxp += 768;
        }

        asm volatile("barrier.cluster.arrive.aligned;" ::: "memory");
        asm volatile("barrier.cluster.wait.aligned;" ::: "memory");
        p ^= 1;
    }
}

// ---------------- head ----------------
__global__ void head_kernel(const float* __restrict__ hT, const float* __restrict__ W,
                            const float* __restrict__ bias, float* __restrict__ out)
{
    int b = blockIdx.x;
    int o = threadIdx.x;   // 96 threads
    const float* h = hT + b * 256;
    const float* w = W + o * 256;
    float s = bias[o];
#pragma unroll 8
    for (int j = 0; j < 256; j++) s = fmaf(h[j], w[j], s);
    out[b * 96 + o] = s;
}

// ---------------- launch ----------------
extern "C" void kernel_launch(void* const* d_in, const int* in_sizes, int n_in,
                              void* d_out, int out_size)
{
    const float* x        = (const float*)d_in[0];
    const float* snn_w    = (const float*)d_in[1];
    const float* snn_b    = (const float*)d_in[2];
    const float* gru_wih  = (const float*)d_in[3];
    const float* gru_whh  = (const float*)d_in[4];
    const float* gru_bih  = (const float*)d_in[5];
    const float* gru_bhh  = (const float*)d_in[6];
    const float* head_w   = (const float*)d_in[7];
    const float* head_b   = (const float*)d_in[8];
    float* out = (float*)d_out;

    float *cur, *gxb, *hTb;
    __nv_bfloat16 *Ae, *Be;
    cudaGetSymbolAddress((void**)&cur, g_cur);
    cudaGetSymbolAddress((void**)&Ae,  g_Ae);
    cudaGetSymbolAddress((void**)&Be,  g_Be);
    cudaGetSymbolAddress((void**)&gxb, g_gx);
    cudaGetSymbolAddress((void**)&hTb, g_hT);

    // 1) cur = x @ snn_w^T + snn_b   (fp32 f32x2 — spike thresholds are error-sensitive)
    gemm_f32x2_kernel<<<dim3(H_ / 128, (B_ * T_) / 128), 512>>>(x, snn_w, snn_b, cur, C_, H_);
    // 2) x -> A' split columns
    copyx_split_kernel<<<(B_ * T_ * 16) / 256, 256>>>(x, Ae);
    // 3) LIF scan -> A' spike columns (exact bf16)
    lif_kernel<<<128, 128>>>(cur, Ae);
    // 4) wih -> B' split columns
    wih_split_kernel<<<(768 * 320) / 256, 256>>>(gru_wih, Be);
    // 5) gx = A' @ B'^T + bih  (mma.sync bf16 HMMA, split-fp32 accuracy)
    gemm_mma_kernel<<<dim3(768 / 128, (B_ * T_) / 128), 256>>>(Ae, Be, gru_bih, gxb);
    // 6) GRU scan (cluster-of-4 persistent, weights in registers)
    gru_kernel<<<128, 384>>>(gxb, gru_whh, gru_bhh, hTb);
    // 7) head
    head_kernel<<<B_, HOR_>>>(hTb, head_w, head_b, out);
}